// round 8
// baseline (speedup 1.0000x reference)
#include <cuda_runtime.h>
#include <cstdint>

// Problem constants
#define BH   24
#define SEQ  4096
#define DD   128
#define FF   256
#define CHK  128
#define NC   32
#define ROWS (BH*SEQ)      // 98304
#define FD   (FF*DD)       // 32768

// ---------------- scratch (device globals; no runtime allocation) ----------
__device__ float g_qphi[(size_t)ROWS * FF];
__device__ float g_kphi[(size_t)ROWS * FF];
__device__ float g_P   [(size_t)BH * (NC+1) * FD];   // TRANSPOSED slabs: [d][f]
__device__ float g_w1t [FF * DD];
__device__ float g_w2t [FF * FF];

#define GP  36    // k-chunk tile stride  (mod 32 == 4 -> conflict-free frag reads)
#define GPT 37    // transposed k-chunk tile stride
#define AP  132   // full A / Q tile stride (mod 32 == 4)
#define VP  133   // transposed V stride
#define HP  260   // fused h stride (mod 32 == 4)

__device__ __forceinline__ uint32_t f2tf32(float x) {
    uint32_t r; asm("cvt.rna.tf32.f32 %0, %1;" : "=r"(r) : "f"(x)); return r;
}
__device__ __forceinline__ void mma8(float* c, const uint32_t* a, const uint32_t* b) {
    asm volatile(
        "mma.sync.aligned.m16n8k8.row.col.f32.tf32.tf32.f32 "
        "{%0,%1,%2,%3}, {%4,%5,%6,%7}, {%8,%9}, {%0,%1,%2,%3};"
        : "+f"(c[0]), "+f"(c[1]), "+f"(c[2]), "+f"(c[3])
        : "r"(a[0]), "r"(a[1]), "r"(a[2]), "r"(a[3]), "r"(b[0]), "r"(b[1]));
}

// ---------------------------------------------------------------------------
// phi_fused: one block per 128 rows.
//   Hs = silu(X @ w1t^T + b1)   (tf32, kept in smem)
//   C  = Hs @ w2t^T + b2        (written to gmem)
// 8 warps 2x4, warp tile 64x32, two 128-col n-passes per stage.
// ---------------------------------------------------------------------------
#define FS_QS    0                         // 128*AP  u32
#define FS_HS    (128*AP)                  // 128*HP  u32
#define FS_BS    (128*AP + 128*HP)         // 128*GP  u32
#define FS_BYTES ((128*AP + 128*HP + 128*GP) * 4)   // 219136

__global__ __launch_bounds__(256, 1) void phi_fused(
    const float* __restrict__ X,
    const float* __restrict__ w1t, const float* __restrict__ b1,
    const float* __restrict__ w2t, const float* __restrict__ b2,
    float* __restrict__ C)
{
    extern __shared__ uint32_t smx[];
    uint32_t* Qs = smx + FS_QS;
    uint32_t* Hs = smx + FS_HS;
    uint32_t* Bs = smx + FS_BS;

    const int t    = threadIdx.x;
    const int lane = t & 31;
    const int wid  = t >> 5;
    const int wm   = wid >> 2;
    const int wn   = wid & 3;
    const int g    = lane >> 2;
    const int tig  = lane & 3;
    const int row0 = blockIdx.x * 128;

    // ---- stage q tile [128][128] as tf32 ----
#pragma unroll
    for (int r = 0; r < 16; r++) {
        int slot = t + r * 256;          // 4096 float4 slots
        int row  = slot >> 5;            // 0..127
        int c4   = (slot & 31) << 2;     // 0..124
        float4 v = *(const float4*)(X + (size_t)(row0 + row) * DD + c4);
        uint32_t* p = &Qs[row * AP + c4];
        p[0] = f2tf32(v.x); p[1] = f2tf32(v.y);
        p[2] = f2tf32(v.z); p[3] = f2tf32(v.w);
    }

    // =============== Stage A: h = silu(q @ w1t^T + b1) ===============
#pragma unroll
    for (int nh = 0; nh < 2; nh++) {
        float acc[4][4][4];
#pragma unroll
        for (int mt = 0; mt < 4; mt++)
#pragma unroll
            for (int nt = 0; nt < 4; nt++)
#pragma unroll
                for (int e = 0; e < 4; e++) acc[mt][nt][e] = 0.f;

#pragma unroll
        for (int k0 = 0; k0 < DD; k0 += 32) {
            __syncthreads();
            // Bs <- w1t rows [nh*128 .. +128), cols [k0..k0+32)
#pragma unroll
            for (int r = 0; r < 4; r++) {
                int slot = t + r * 256;
                int row  = slot >> 3;
                int c4   = (slot & 7) << 2;
                float4 v = *(const float4*)(w1t + (size_t)(nh * 128 + row) * DD + k0 + c4);
                uint32_t* p = &Bs[row * GP + c4];
                p[0] = f2tf32(v.x); p[1] = f2tf32(v.y);
                p[2] = f2tf32(v.z); p[3] = f2tf32(v.w);
            }
            __syncthreads();
#pragma unroll
            for (int ks = 0; ks < 4; ks++) {
                int kc = k0 + ks * 8 + tig;   // absolute col in Qs
                int kb = ks * 8 + tig;        // local col in Bs
                uint32_t af[4][4];
#pragma unroll
                for (int mt = 0; mt < 4; mt++) {
                    int base = (wm * 64 + mt * 16 + g) * AP + kc;
                    af[mt][0] = Qs[base];
                    af[mt][1] = Qs[base + 8 * AP];
                    af[mt][2] = Qs[base + 4];
                    af[mt][3] = Qs[base + 8 * AP + 4];
                }
                uint32_t bf[4][2];
#pragma unroll
                for (int nt = 0; nt < 4; nt++) {
                    int base = (wn * 32 + nt * 8 + g) * GP + kb;
                    bf[nt][0] = Bs[base];
                    bf[nt][1] = Bs[base + 4];
                }
#pragma unroll
                for (int mt = 0; mt < 4; mt++)
#pragma unroll
                    for (int nt = 0; nt < 4; nt++)
                        mma8(acc[mt][nt], af[mt], bf[nt]);
            }
        }
        // silu + store h (tf32) into Hs
#pragma unroll
        for (int mt = 0; mt < 4; mt++) {
#pragma unroll
            for (int nt = 0; nt < 4; nt++) {
                int n0  = wm * 64 + mt * 16 + g;
                int col = nh * 128 + wn * 32 + nt * 8 + tig * 2;
                float b0v = b1[col], b1v = b1[col + 1];
                float x0 = acc[mt][nt][0] + b0v;
                float x1 = acc[mt][nt][1] + b1v;
                float x2 = acc[mt][nt][2] + b0v;
                float x3 = acc[mt][nt][3] + b1v;
                x0 = x0 / (1.f + __expf(-x0));
                x1 = x1 / (1.f + __expf(-x1));
                x2 = x2 / (1.f + __expf(-x2));
                x3 = x3 / (1.f + __expf(-x3));
                Hs[n0 * HP + col]           = f2tf32(x0);
                Hs[n0 * HP + col + 1]       = f2tf32(x1);
                Hs[(n0 + 8) * HP + col]     = f2tf32(x2);
                Hs[(n0 + 8) * HP + col + 1] = f2tf32(x3);
            }
        }
    }
    __syncthreads();   // Hs complete

    // =============== Stage B: C = h @ w2t^T + b2 ===============
#pragma unroll
    for (int nh = 0; nh < 2; nh++) {
        float acc[4][4][4];
#pragma unroll
        for (int mt = 0; mt < 4; mt++)
#pragma unroll
            for (int nt = 0; nt < 4; nt++)
#pragma unroll
                for (int e = 0; e < 4; e++) acc[mt][nt][e] = 0.f;

#pragma unroll
        for (int k0 = 0; k0 < FF; k0 += 32) {
            __syncthreads();
#pragma unroll
            for (int r = 0; r < 4; r++) {
                int slot = t + r * 256;
                int row  = slot >> 3;
                int c4   = (slot & 7) << 2;
                float4 v = *(const float4*)(w2t + (size_t)(nh * 128 + row) * FF + k0 + c4);
                uint32_t* p = &Bs[row * GP + c4];
                p[0] = f2tf32(v.x); p[1] = f2tf32(v.y);
                p[2] = f2tf32(v.z); p[3] = f2tf32(v.w);
            }
            __syncthreads();
#pragma unroll
            for (int ks = 0; ks < 4; ks++) {
                int kc = k0 + ks * 8 + tig;
                int kb = ks * 8 + tig;
                uint32_t af[4][4];
#pragma unroll
                for (int mt = 0; mt < 4; mt++) {
                    int base = (wm * 64 + mt * 16 + g) * HP + kc;
                    af[mt][0] = Hs[base];
                    af[mt][1] = Hs[base + 8 * HP];
                    af[mt][2] = Hs[base + 4];
                    af[mt][3] = Hs[base + 8 * HP + 4];
                }
                uint32_t bf[4][2];
#pragma unroll
                for (int nt = 0; nt < 4; nt++) {
                    int base = (wn * 32 + nt * 8 + g) * GP + kb;
                    bf[nt][0] = Bs[base];
                    bf[nt][1] = Bs[base + 4];
                }
#pragma unroll
                for (int mt = 0; mt < 4; mt++)
#pragma unroll
                    for (int nt = 0; nt < 4; nt++)
                        mma8(acc[mt][nt], af[mt], bf[nt]);
            }
        }
        // bias + store to gmem
#pragma unroll
        for (int mt = 0; mt < 4; mt++) {
#pragma unroll
            for (int nt = 0; nt < 4; nt++) {
                int row = row0 + wm * 64 + mt * 16 + g;
                int col = nh * 128 + wn * 32 + nt * 8 + tig * 2;
                float b0v = b2[col], b1v = b2[col + 1];
                float2 o01, o23;
                o01.x = acc[mt][nt][0] + b0v;
                o01.y = acc[mt][nt][1] + b1v;
                o23.x = acc[mt][nt][2] + b0v;
                o23.y = acc[mt][nt][3] + b1v;
                *(float2*)(C + (size_t)row * FF + col)       = o01;
                *(float2*)(C + (size_t)(row + 8) * FF + col) = o23;
            }
        }
    }
}

// ---------------------------------------------------------------------------
// Transpose W [K,N] -> Wt [N,K]
// ---------------------------------------------------------------------------
__global__ void transpose_kernel(const float* __restrict__ W,
                                 float* __restrict__ Wt, int K, int N)
{
    int idx = blockIdx.x * blockDim.x + threadIdx.x;
    if (idx >= K * N) return;
    int kk = idx / N;
    int n  = idx - kk * N;
    Wt[(size_t)n * K + kk] = W[idx];
}

// ---------------------------------------------------------------------------
// chunk_state (tensor cores): S^T[d][f] = sum_m V[m][d] * Kphi[m][f]
// ---------------------------------------------------------------------------
__global__ __launch_bounds__(256) void chunk_state_tc(
    const float* __restrict__ kphi, const float* __restrict__ vin,
    float* __restrict__ P)
{
    __shared__ uint32_t At[128 * GPT];
    __shared__ uint32_t Bt[128 * GPT];

    const int t    = threadIdx.x;
    const int lane = t & 31;
    const int wid  = t >> 5;
    const int wm   = wid >> 2;
    const int wn   = wid & 3;
    const int g    = lane >> 2;
    const int tig  = lane & 3;
    const int hc   = blockIdx.x;
    const int h    = hc >> 5;
    const int c    = hc & 31;
    const int f0   = blockIdx.y * 128;
    const int pos0 = h * SEQ + c * CHK;

    float acc[4][4][4];
#pragma unroll
    for (int mt = 0; mt < 4; mt++)
#pragma unroll
        for (int nt = 0; nt < 4; nt++)
#pragma unroll
            for (int e = 0; e < 4; e++) acc[mt][nt][e] = 0.f;

    for (int m0 = 0; m0 < CHK; m0 += 32) {
#pragma unroll
        for (int r = 0; r < 4; r++) {
            int slot = t + r * 256;
            int m    = slot >> 5;
            int x4   = (slot & 31) << 2;
            float4 vv = *(const float4*)(vin + (size_t)(pos0 + m0 + m) * DD + x4);
            At[(x4+0)*GPT + m] = f2tf32(vv.x);
            At[(x4+1)*GPT + m] = f2tf32(vv.y);
            At[(x4+2)*GPT + m] = f2tf32(vv.z);
            At[(x4+3)*GPT + m] = f2tf32(vv.w);
            float4 kk = *(const float4*)(kphi + (size_t)(pos0 + m0 + m) * FF + f0 + x4);
            Bt[(x4+0)*GPT + m] = f2tf32(kk.x);
            Bt[(x4+1)*GPT + m] = f2tf32(kk.y);
            Bt[(x4+2)*GPT + m] = f2tf32(kk.z);
            Bt[(x4+3)*GPT + m] = f2tf32(kk.w);
        }
        __syncthreads();
#pragma unroll
        for (int ks = 0; ks < 4; ks++) {
            int kc = ks * 8 + tig;
            uint32_t af[4][4];
#pragma unroll
            for (int mt = 0; mt < 4; mt++) {
                int base = (wm * 64 + mt * 16 + g) * GPT + kc;
                af[mt][0] = At[base];
                af[mt][1] = At[base + 8 * GPT];
                af[mt][2] = At[base + 4];
                af[mt][3] = At[base + 8 * GPT + 4];
            }
            uint32_t bf[4][2];
#pragma unroll
            for (int nt = 0; nt < 4; nt++) {
                int base = (wn * 32 + nt * 8 + g) * GPT + kc;
                bf[nt][0] = Bt[base];
                bf[nt][1] = Bt[base + 4];
            }
#pragma unroll
            for (int mt = 0; mt < 4; mt++)
#pragma unroll
                for (int nt = 0; nt < 4; nt++)
                    mma8(acc[mt][nt], af[mt], bf[nt]);
        }
        __syncthreads();
    }

    float* S = P + ((size_t)(h * (NC + 1)) + (c + 1)) * FD;
#pragma unroll
    for (int mt = 0; mt < 4; mt++) {
#pragma unroll
        for (int nt = 0; nt < 4; nt++) {
            int d   = wm * 64 + mt * 16 + g;
            int col = f0 + wn * 32 + nt * 8 + tig * 2;
            float2 o01; o01.x = acc[mt][nt][0]; o01.y = acc[mt][nt][1];
            float2 o23; o23.x = acc[mt][nt][2]; o23.y = acc[mt][nt][3];
            *(float2*)(S + (size_t)d * FF + col)       = o01;
            *(float2*)(S + (size_t)(d + 8) * FF + col) = o23;
        }
    }
}

// ---------------------------------------------------------------------------
// Inclusive prefix over chunk slabs.
// ---------------------------------------------------------------------------
__global__ void prefix_kernel(float* __restrict__ P)
{
    const int h = blockIdx.y;
    const int e = blockIdx.x * 256 + threadIdx.x;
    float* base = P + (size_t)h * (NC + 1) * FD;
    base[e] = 0.f;
    float acc = 0.f;
#pragma unroll
    for (int c = 1; c <= NC; c++) {
        acc += base[(size_t)c * FD + e];
        base[(size_t)c * FD + e] = acc;
    }
}

// ---------------------------------------------------------------------------
// output_tc (verified R7): per (head, chunk) block, all-tensor-core.
// ---------------------------------------------------------------------------
#define OSM_BYTES ((128*AP + 128*VP) * 4)   // 135680

__global__ __launch_bounds__(256, 1) void output_tc(
    const float* __restrict__ qphi, const float* __restrict__ kphi,
    const float* __restrict__ vin,  const float* __restrict__ P,
    float* __restrict__ out)
{
    extern __shared__ uint32_t smx[];
    uint32_t* Abuf = smx;
    uint32_t* Vt   = smx + 128 * AP;
    uint32_t* S1Q  = Vt;
    uint32_t* S1K  = Vt + 128 * GP;
    uint32_t* S3Q  = Abuf;
    uint32_t* S3B1 = Abuf + 128 * GP;
    uint32_t* S3B2 = Abuf + 2 * 128 * GP;

    const int t    = threadIdx.x;
    const int lane = t & 31;
    const int wid  = t >> 5;
    const int wm   = wid >> 2;
    const int wn   = wid & 3;
    const int g    = lane >> 2;
    const int tig  = lane & 3;
    const int hc   = blockIdx.x;
    const int h    = hc >> 5;
    const int c    = hc & 31;
    const int pos0 = h * SEQ + c * CHK;

    float accA[4][4][4];
#pragma unroll
    for (int mt = 0; mt < 4; mt++)
#pragma unroll
        for (int nt = 0; nt < 4; nt++)
#pragma unroll
            for (int e = 0; e < 4; e++) accA[mt][nt][e] = 0.f;

    for (int f0 = 0; f0 < FF; f0 += 32) {
        __syncthreads();
#pragma unroll
        for (int r = 0; r < 4; r++) {
            int slot = t + r * 256;
            int row  = slot >> 3;
            int c4   = (slot & 7) << 2;
            float4 qv = *(const float4*)(qphi + (size_t)(pos0 + row) * FF + f0 + c4);
            uint32_t* pq = &S1Q[row * GP + c4];
            pq[0] = f2tf32(qv.x); pq[1] = f2tf32(qv.y);
            pq[2] = f2tf32(qv.z); pq[3] = f2tf32(qv.w);
            float4 kv = *(const float4*)(kphi + (size_t)(pos0 + row) * FF + f0 + c4);
            uint32_t* pk = &S1K[row * GP + c4];
            pk[0] = f2tf32(kv.x); pk[1] = f2tf32(kv.y);
            pk[2] = f2tf32(kv.z); pk[3] = f2tf32(kv.w);
        }
        __syncthreads();
#pragma unroll
        for (int ks = 0; ks < 4; ks++) {
            int kc = ks * 8 + tig;
            uint32_t af[4][4];
#pragma unroll
            for (int mt = 0; mt < 4; mt++) {
                int base = (wm * 64 + mt * 16 + g) * GP + kc;
                af[mt][0] = S1Q[base];
                af[mt][1] = S1Q[base + 8 * GP];
                af[mt][2] = S1Q[base + 4];
                af[mt][3] = S1Q[base + 8 * GP + 4];
            }
            uint32_t bf[4][2];
#pragma unroll
            for (int nt = 0; nt < 4; nt++) {
                int base = (wn * 32 + nt * 8 + g) * GP + kc;
                bf[nt][0] = S1K[base];
                bf[nt][1] = S1K[base + 4];
            }
#pragma unroll
            for (int mt = 0; mt < 4; mt++)
#pragma unroll
                for (int nt = 0; nt < 4; nt++)
                    mma8(accA[mt][nt], af[mt], bf[nt]);
        }
    }
    __syncthreads();

#pragma unroll
    for (int mt = 0; mt < 4; mt++) {
#pragma unroll
        for (int nt = 0; nt < 4; nt++) {
            int n0 = wm * 64 + mt * 16 + g;
            int m0 = wn * 32 + nt * 8 + tig * 2;
            Abuf[n0 * AP + m0]           = f2tf32(accA[mt][nt][0]);
            Abuf[n0 * AP + m0 + 1]       = f2tf32(accA[mt][nt][1]);
            Abuf[(n0 + 8) * AP + m0]     = f2tf32(accA[mt][nt][2]);
            Abuf[(n0 + 8) * AP + m0 + 1] = f2tf32(accA[mt][nt][3]);
        }
    }
#pragma unroll
    for (int r = 0; r < 16; r++) {
        int slot = t + r * 256;
        int m    = slot >> 5;
        int d4   = (slot & 31) << 2;
        float4 vv = *(const float4*)(vin + (size_t)(pos0 + m) * DD + d4);
        Vt[(d4+0)*VP + m] = f2tf32(vv.x);
        Vt[(d4+1)*VP + m] = f2tf32(vv.y);
        Vt[(d4+2)*VP + m] = f2tf32(vv.z);
        Vt[(d4+3)*VP + m] = f2tf32(vv.w);
    }
    __syncthreads();

    float acc1[4][4][4], acc2[4][4][4];
#pragma unroll
    for (int mt = 0; mt < 4; mt++)
#pragma unroll
        for (int nt = 0; nt < 4; nt++)
#pragma unroll
            for (int e = 0; e < 4; e++) { acc1[mt][nt][e] = 0.f; acc2[mt][nt][e] = 0.f; }

#pragma unroll
    for (int kch = 0; kch < 4; kch++) {
#pragma unroll
        for (int ks = 0; ks < 4; ks++) {
            int kc = kch * 32 + ks * 8 + tig;
            uint32_t lo[4][4], up[4][4];
#pragma unroll
            for (int mt = 0; mt < 4; mt++) {
                int nA = wm * 64 + mt * 16 + g;
                int nB = nA + 8;
                uint32_t a0 = Abuf[nA * AP + kc];
                uint32_t a1 = Abuf[nB * AP + kc];
                uint32_t a2 = Abuf[nA * AP + kc + 4];
                uint32_t a3 = Abuf[nB * AP + kc + 4];
                lo[mt][0] = (kc     <= nA) ? a0 : 0u;
                lo[mt][1] = (kc     <= nB) ? a1 : 0u;
                lo[mt][2] = (kc + 4 <= nA) ? a2 : 0u;
                lo[mt][3] = (kc + 4 <= nB) ? a3 : 0u;
                up[mt][0] = (kc     >= nA) ? a0 : 0u;
                up[mt][1] = (kc     >= nB) ? a1 : 0u;
                up[mt][2] = (kc + 4 >= nA) ? a2 : 0u;
                up[mt][3] = (kc + 4 >= nB) ? a3 : 0u;
            }
            uint32_t bf[4][2];
#pragma unroll
            for (int nt = 0; nt < 4; nt++) {
                int base = (wn * 32 + nt * 8 + g) * VP + kc;
                bf[nt][0] = Vt[base];
                bf[nt][1] = Vt[base + 4];
            }
#pragma unroll
            for (int mt = 0; mt < 4; mt++)
#pragma unroll
                for (int nt = 0; nt < 4; nt++) {
                    mma8(acc1[mt][nt], lo[mt], bf[nt]);
                    mma8(acc2[mt][nt], up[mt], bf[nt]);
                }
        }
    }
    __syncthreads();

    const float* Pbase = P + (size_t)h * (NC + 1) * FD;
    const float* Pexc  = Pbase + (size_t)c * FD;
    const float* Pinc  = Pbase + (size_t)(c + 1) * FD;
    const float* Ptot  = Pbase + (size_t)NC * FD;

    for (int f0 = 0; f0 < FF; f0 += 32) {
#pragma unroll
        for (int r = 0; r < 4; r++) {
            int slot = t + r * 256;
            int row  = slot >> 3;
            int c4   = (slot & 7) << 2;
            float4 qv = *(const float4*)(qphi + (size_t)(pos0 + row) * FF + f0 + c4);
            uint32_t* pq = &S3Q[row * GP + c4];
            pq[0] = f2tf32(qv.x); pq[1] = f2tf32(qv.y);
            pq[2] = f2tf32(qv.z); pq[3] = f2tf32(qv.w);
            size_t go = (size_t)row * FF + f0 + c4;
            float4 ev = *(const float4*)(Pexc + go);
            uint32_t* p1 = &S3B1[row * GP + c4];
            p1[0] = f2tf32(ev.x); p1[1] = f2tf32(ev.y);
            p1[2] = f2tf32(ev.z); p1[3] = f2tf32(ev.w);
            float4 iv = *(const float4*)(Pinc + go);
            float4 tv = *(const float4*)(Ptot + go);
            uint32_t* p2 = &S3B2[row * GP + c4];
            p2[0] = f2tf32(tv.x - iv.x); p2[1] = f2tf32(tv.y - iv.y);
            p2[2] = f2tf32(tv.z - iv.z); p2[3] = f2tf32(tv.w - iv.w);
        }
        __syncthreads();
#pragma unroll
        for (int ks = 0; ks < 4; ks++) {
            int kc = ks * 8 + tig;
            uint32_t af[4][4];
#pragma unroll
            for (int mt = 0; mt < 4; mt++) {
                int base = (wm * 64 + mt * 16 + g) * GP + kc;
                af[mt][0] = S3Q[base];
                af[mt][1] = S3Q[base + 8 * GP];
                af[mt][2] = S3Q[base + 4];
                af[mt][3] = S3Q[base + 8 * GP + 4];
            }
            uint32_t b1[4][2], b2[4][2];
#pragma unroll
            for (int nt = 0; nt < 4; nt++) {
                int base = (wn * 32 + nt * 8 + g) * GP + kc;
                b1[nt][0] = S3B1[base];
                b1[nt][1] = S3B1[base + 4];
                b2[nt][0] = S3B2[base];
                b2[nt][1] = S3B2[base + 4];
            }
#pragma unroll
            for (int mt = 0; mt < 4; mt++)
#pragma unroll
                for (int nt = 0; nt < 4; nt++) {
                    mma8(acc1[mt][nt], af[mt], b1[nt]);
                    mma8(acc2[mt][nt], af[mt], b2[nt]);
                }
        }
        __syncthreads();
    }

#pragma unroll
    for (int mt = 0; mt < 4; mt++) {
#pragma unroll
        for (int nt = 0; nt < 4; nt++) {
            int n0  = wm * 64 + mt * 16 + g;
            int d0  = wn * 32 + nt * 8 + tig * 2;
            int posA = c * CHK + n0;
            int posB = posA + 8;
            float s1a = 1.f / (float)(posA + 1);
            float s2a = 1.f / (float)(SEQ - posA);
            float s1b = 1.f / (float)(posB + 1);
            float s2b = 1.f / (float)(SEQ - posB);
            float2 oA, oB;
            oA.x = acc1[mt][nt][0] * s1a + acc2[mt][nt][0] * s2a;
            oA.y = acc1[mt][nt][1] * s1a + acc2[mt][nt][1] * s2a;
            oB.x = acc1[mt][nt][2] * s1b + acc2[mt][nt][2] * s2b;
            oB.y = acc1[mt][nt][3] * s1b + acc2[mt][nt][3] * s2b;
            *(float2*)(out + (size_t)(pos0 + n0) * DD + d0)     = oA;
            *(float2*)(out + (size_t)(pos0 + n0 + 8) * DD + d0) = oB;
        }
    }
}

// ---------------------------------------------------------------------------
extern "C" void kernel_launch(void* const* d_in, const int* in_sizes, int n_in,
                              void* d_out, int out_size)
{
    (void)out_size;
    int big[3] = {0, 1, 2}; int nbig = 0;
    int iw1 = -1, iw2 = -1, ibias[2] = {-1, -1}; int nb = 0;
    for (int i = 0; i < n_in; i++) {
        long long s = in_sizes[i];
        if ((s == 12582912LL || s == 50331648LL) && nbig < 3) big[nbig++] = i;
        else if (s == 32768LL  || s == 131072LL) iw1 = i;
        else if (s == 65536LL  || s == 262144LL) iw2 = i;
        else if ((s == 256LL   || s == 1024LL) && nb < 2) ibias[nb++] = i;
    }
    if (nbig != 3 || iw1 < 0 || iw2 < 0 || nb != 2) {
        big[0] = 0; big[1] = 1; big[2] = 2;
        iw1 = 3; ibias[0] = 4; iw2 = 5; ibias[1] = 6;
    }
    const float *q, *k;
    if (big[0] == 0) {
        q = (const float*)d_in[big[0]];
        k = (const float*)d_in[big[1]];
    } else {
        k = (const float*)d_in[big[0]];
        q = (const float*)d_in[big[1]];
    }
    const float* v  = (const float*)d_in[big[2]];
    const float* w1 = (const float*)d_in[iw1];
    const float* b1 = (const float*)d_in[ibias[0]];
    const float* w2 = (const float*)d_in[iw2];
    const float* b2 = (const float*)d_in[ibias[1]];
    float* out = (float*)d_out;

    float *qphi, *kphi, *P, *w1t, *w2t;
    cudaGetSymbolAddress((void**)&qphi, g_qphi);
    cudaGetSymbolAddress((void**)&kphi, g_kphi);
    cudaGetSymbolAddress((void**)&P,    g_P);
    cudaGetSymbolAddress((void**)&w1t,  g_w1t);
    cudaGetSymbolAddress((void**)&w2t,  g_w2t);

    cudaFuncSetAttribute(phi_fused,
                         cudaFuncAttributeMaxDynamicSharedMemorySize, FS_BYTES);
    cudaFuncSetAttribute(output_tc,
                         cudaFuncAttributeMaxDynamicSharedMemorySize, OSM_BYTES);

    transpose_kernel<<<(DD*FF + 255)/256, 256>>>(w1, w1t, DD, FF);
    transpose_kernel<<<(FF*FF + 255)/256, 256>>>(w2, w2t, FF, FF);

    // fused phi (q and k paths)
    phi_fused<<<ROWS / 128, 256, FS_BYTES>>>(q, w1t, b1, w2t, b2, qphi);
    phi_fused<<<ROWS / 128, 256, FS_BYTES>>>(k, w1t, b1, w2t, b2, kphi);

    chunk_state_tc<<<dim3(BH * NC, 2), 256>>>(kphi, v, P);
    prefix_kernel<<<dim3(FD / 256, BH), 256>>>(P);

    output_tc<<<BH * NC, 256, OSM_BYTES>>>(qphi, kphi, v, P, out);
}

// round 9
// speedup vs baseline: 1.0186x; 1.0186x over previous
#include <cuda_runtime.h>
#include <cstdint>

// Problem constants
#define BH   24
#define SEQ  4096
#define DD   128
#define FF   256
#define CHK  128
#define NC   32
#define ROWS (BH*SEQ)      // 98304
#define FD   (FF*DD)       // 32768
#define NBLK (ROWS/128)    // 768

// ---------------- scratch (device globals; no runtime allocation) ----------
__device__ float g_hq  [(size_t)ROWS * FF];
__device__ float g_hk  [(size_t)ROWS * FF];
__device__ float g_qphi[(size_t)ROWS * FF];
__device__ float g_kphi[(size_t)ROWS * FF];
__device__ float g_P   [(size_t)BH * (NC+1) * FD];   // TRANSPOSED slabs: [d][f]
__device__ float g_w1t [FF * DD];
__device__ float g_w2t [FF * FF];

#define GP  36    // k-chunk tile stride  (mod 32 == 4 -> conflict-free frag reads)
#define GPT 37    // transposed k-chunk tile stride
#define AP  132   // 128-wide tile stride (mod 32 == 4)
#define VP  133   // transposed V stride
#define HP  260   // 256-wide tile stride (mod 32 == 4)

__device__ __forceinline__ uint32_t f2tf32(float x) {
    uint32_t r; asm("cvt.rna.tf32.f32 %0, %1;" : "=r"(r) : "f"(x)); return r;
}
__device__ __forceinline__ void mma8(float* c, const uint32_t* a, const uint32_t* b) {
    asm volatile(
        "mma.sync.aligned.m16n8k8.row.col.f32.tf32.tf32.f32 "
        "{%0,%1,%2,%3}, {%4,%5,%6,%7}, {%8,%9}, {%0,%1,%2,%3};"
        : "+f"(c[0]), "+f"(c[1]), "+f"(c[2]), "+f"(c[3])
        : "r"(a[0]), "r"(a[1]), "r"(a[2]), "r"(a[3]), "r"(b[0]), "r"(b[1]));
}

// ---------------------------------------------------------------------------
// phiA: h = silu(X @ w1t^T + b1).  Grid 2*NBLK (q then k).
// Entire w1t (256x128) + X tile (128x128) resident in smem; ONE sync total.
// 8 warps 2x4; two n-passes of 128; K=128 contiguous (16 ks, no syncs).
// ---------------------------------------------------------------------------
#define PA_XS    0
#define PA_WS    (128*AP)
#define PA_BYTES ((128*AP + 256*AP) * 4)    // 202752

__global__ __launch_bounds__(256, 1) void phiA(
    const float* __restrict__ Xq, const float* __restrict__ Xk,
    const float* __restrict__ w1t, const float* __restrict__ b1,
    float* __restrict__ Hq, float* __restrict__ Hk)
{
    extern __shared__ uint32_t smx[];
    uint32_t* Xs = smx + PA_XS;
    uint32_t* Ws = smx + PA_WS;

    const int t    = threadIdx.x;
    const int lane = t & 31;
    const int wid  = t >> 5;
    const int wm   = wid >> 2;
    const int wn   = wid & 3;
    const int g    = lane >> 2;
    const int tig  = lane & 3;
    const int bx   = blockIdx.x;
    const bool isK = (bx >= NBLK);
    const int row0 = (isK ? bx - NBLK : bx) * 128;
    const float* X = isK ? Xk : Xq;
    float* H       = isK ? Hk : Hq;

    // stage X tile [128][128]
#pragma unroll
    for (int r = 0; r < 16; r++) {
        int slot = t + r * 256;
        int row  = slot >> 5;
        int c4   = (slot & 31) << 2;
        float4 v = *(const float4*)(X + (size_t)(row0 + row) * DD + c4);
        uint32_t* p = &Xs[row * AP + c4];
        p[0] = f2tf32(v.x); p[1] = f2tf32(v.y);
        p[2] = f2tf32(v.z); p[3] = f2tf32(v.w);
    }
    // stage full w1t [256][128]
#pragma unroll
    for (int r = 0; r < 32; r++) {
        int slot = t + r * 256;
        int row  = slot >> 5;           // 0..255
        int c4   = (slot & 31) << 2;
        float4 v = *(const float4*)(w1t + (size_t)row * DD + c4);
        uint32_t* p = &Ws[row * AP + c4];
        p[0] = f2tf32(v.x); p[1] = f2tf32(v.y);
        p[2] = f2tf32(v.z); p[3] = f2tf32(v.w);
    }
    __syncthreads();

#pragma unroll
    for (int np = 0; np < 2; np++) {
        float acc[4][4][4];
#pragma unroll
        for (int mt = 0; mt < 4; mt++)
#pragma unroll
            for (int nt = 0; nt < 4; nt++)
#pragma unroll
                for (int e = 0; e < 4; e++) acc[mt][nt][e] = 0.f;

#pragma unroll
        for (int ks = 0; ks < 16; ks++) {
            int kc = ks * 8 + tig;
            uint32_t af[4][4];
#pragma unroll
            for (int mt = 0; mt < 4; mt++) {
                int base = (wm * 64 + mt * 16 + g) * AP + kc;
                af[mt][0] = Xs[base];
                af[mt][1] = Xs[base + 8 * AP];
                af[mt][2] = Xs[base + 4];
                af[mt][3] = Xs[base + 8 * AP + 4];
            }
            uint32_t bf[4][2];
#pragma unroll
            for (int nt = 0; nt < 4; nt++) {
                int base = (np * 128 + wn * 32 + nt * 8 + g) * AP + kc;
                bf[nt][0] = Ws[base];
                bf[nt][1] = Ws[base + 4];
            }
#pragma unroll
            for (int mt = 0; mt < 4; mt++)
#pragma unroll
                for (int nt = 0; nt < 4; nt++)
                    mma8(acc[mt][nt], af[mt], bf[nt]);
        }
        // silu + store h
#pragma unroll
        for (int mt = 0; mt < 4; mt++) {
#pragma unroll
            for (int nt = 0; nt < 4; nt++) {
                int row = row0 + wm * 64 + mt * 16 + g;
                int col = np * 128 + wn * 32 + nt * 8 + tig * 2;
                float b0v = b1[col], b1v = b1[col + 1];
                float x0 = acc[mt][nt][0] + b0v;
                float x1 = acc[mt][nt][1] + b1v;
                float x2 = acc[mt][nt][2] + b0v;
                float x3 = acc[mt][nt][3] + b1v;
                x0 = x0 / (1.f + __expf(-x0));
                x1 = x1 / (1.f + __expf(-x1));
                x2 = x2 / (1.f + __expf(-x2));
                x3 = x3 / (1.f + __expf(-x3));
                float2 o01, o23;
                o01.x = x0; o01.y = x1;
                o23.x = x2; o23.y = x3;
                *(float2*)(H + (size_t)row * FF + col)       = o01;
                *(float2*)(H + (size_t)(row + 8) * FF + col) = o23;
            }
        }
    }
}

// ---------------------------------------------------------------------------
// phiB: phi = h @ w2t^T + b2.  Grid 2*NBLK.
// h tile (128x256) resident; w2t staged in 64-row slices; K=256 contiguous.
// 8 warps 2x4; warp tile 64x16 per pass (mt=4, nt=2); 4 n-passes.
// ---------------------------------------------------------------------------
#define PB_HS    0
#define PB_WS    (128*HP)
#define PB_BYTES ((128*HP + 64*HP) * 4)     // 199680

__global__ __launch_bounds__(256, 1) void phiB(
    const float* __restrict__ Hq, const float* __restrict__ Hk,
    const float* __restrict__ w2t, const float* __restrict__ b2,
    float* __restrict__ Cq, float* __restrict__ Ck)
{
    extern __shared__ uint32_t smx[];
    uint32_t* Hs = smx + PB_HS;
    uint32_t* Ws = smx + PB_WS;

    const int t    = threadIdx.x;
    const int lane = t & 31;
    const int wid  = t >> 5;
    const int wm   = wid >> 2;
    const int wn   = wid & 3;
    const int g    = lane >> 2;
    const int tig  = lane & 3;
    const int bx   = blockIdx.x;
    const bool isK = (bx >= NBLK);
    const int row0 = (isK ? bx - NBLK : bx) * 128;
    const float* H = isK ? Hk : Hq;
    float* C       = isK ? Ck : Cq;

    // stage h tile [128][256]
#pragma unroll
    for (int r = 0; r < 32; r++) {
        int slot = t + r * 256;          // 8192 float4 slots
        int row  = slot >> 6;            // 0..127
        int c4   = (slot & 63) << 2;     // 0..252
        float4 v = *(const float4*)(H + (size_t)(row0 + row) * FF + c4);
        uint32_t* p = &Hs[row * HP + c4];
        p[0] = f2tf32(v.x); p[1] = f2tf32(v.y);
        p[2] = f2tf32(v.z); p[3] = f2tf32(v.w);
    }

#pragma unroll
    for (int np = 0; np < 4; np++) {
        __syncthreads();   // previous pass done reading Ws
        // stage w2t slice rows [np*64 .. +64), all 256 k
#pragma unroll
        for (int r = 0; r < 16; r++) {
            int slot = t + r * 256;      // 4096 slots
            int row  = slot >> 6;        // 0..63
            int c4   = (slot & 63) << 2;
            float4 v = *(const float4*)(w2t + (size_t)(np * 64 + row) * FF + c4);
            uint32_t* p = &Ws[row * HP + c4];
            p[0] = f2tf32(v.x); p[1] = f2tf32(v.y);
            p[2] = f2tf32(v.z); p[3] = f2tf32(v.w);
        }
        __syncthreads();

        float acc[4][2][4];
#pragma unroll
        for (int mt = 0; mt < 4; mt++)
#pragma unroll
            for (int nt = 0; nt < 2; nt++)
#pragma unroll
                for (int e = 0; e < 4; e++) acc[mt][nt][e] = 0.f;

#pragma unroll
        for (int ks = 0; ks < 32; ks++) {
            int kc = ks * 8 + tig;
            uint32_t af[4][4];
#pragma unroll
            for (int mt = 0; mt < 4; mt++) {
                int base = (wm * 64 + mt * 16 + g) * HP + kc;
                af[mt][0] = Hs[base];
                af[mt][1] = Hs[base + 8 * HP];
                af[mt][2] = Hs[base + 4];
                af[mt][3] = Hs[base + 8 * HP + 4];
            }
            uint32_t bf[2][2];
#pragma unroll
            for (int nt = 0; nt < 2; nt++) {
                int base = (wn * 16 + nt * 8 + g) * HP + kc;
                bf[nt][0] = Ws[base];
                bf[nt][1] = Ws[base + 4];
            }
#pragma unroll
            for (int mt = 0; mt < 4; mt++)
#pragma unroll
                for (int nt = 0; nt < 2; nt++)
                    mma8(acc[mt][nt], af[mt], bf[nt]);
        }
        // bias + store
#pragma unroll
        for (int mt = 0; mt < 4; mt++) {
#pragma unroll
            for (int nt = 0; nt < 2; nt++) {
                int row = row0 + wm * 64 + mt * 16 + g;
                int col = np * 64 + wn * 16 + nt * 8 + tig * 2;
                float b0v = b2[col], b1v = b2[col + 1];
                float2 o01, o23;
                o01.x = acc[mt][nt][0] + b0v;
                o01.y = acc[mt][nt][1] + b1v;
                o23.x = acc[mt][nt][2] + b0v;
                o23.y = acc[mt][nt][3] + b1v;
                *(float2*)(C + (size_t)row * FF + col)       = o01;
                *(float2*)(C + (size_t)(row + 8) * FF + col) = o23;
            }
        }
    }
}

// ---------------------------------------------------------------------------
// Transpose W [K,N] -> Wt [N,K]
// ---------------------------------------------------------------------------
__global__ void transpose_kernel(const float* __restrict__ W,
                                 float* __restrict__ Wt, int K, int N)
{
    int idx = blockIdx.x * blockDim.x + threadIdx.x;
    if (idx >= K * N) return;
    int kk = idx / N;
    int n  = idx - kk * N;
    Wt[(size_t)n * K + kk] = W[idx];
}

// ---------------------------------------------------------------------------
// chunk_state (tensor cores): S^T[d][f] = sum_m V[m][d] * Kphi[m][f]
// ---------------------------------------------------------------------------
__global__ __launch_bounds__(256) void chunk_state_tc(
    const float* __restrict__ kphi, const float* __restrict__ vin,
    float* __restrict__ P)
{
    __shared__ uint32_t At[128 * GPT];
    __shared__ uint32_t Bt[128 * GPT];

    const int t    = threadIdx.x;
    const int lane = t & 31;
    const int wid  = t >> 5;
    const int wm   = wid >> 2;
    const int wn   = wid & 3;
    const int g    = lane >> 2;
    const int tig  = lane & 3;
    const int hc   = blockIdx.x;
    const int h    = hc >> 5;
    const int c    = hc & 31;
    const int f0   = blockIdx.y * 128;
    const int pos0 = h * SEQ + c * CHK;

    float acc[4][4][4];
#pragma unroll
    for (int mt = 0; mt < 4; mt++)
#pragma unroll
        for (int nt = 0; nt < 4; nt++)
#pragma unroll
            for (int e = 0; e < 4; e++) acc[mt][nt][e] = 0.f;

    for (int m0 = 0; m0 < CHK; m0 += 32) {
#pragma unroll
        for (int r = 0; r < 4; r++) {
            int slot = t + r * 256;
            int m    = slot >> 5;
            int x4   = (slot & 31) << 2;
            float4 vv = *(const float4*)(vin + (size_t)(pos0 + m0 + m) * DD + x4);
            At[(x4+0)*GPT + m] = f2tf32(vv.x);
            At[(x4+1)*GPT + m] = f2tf32(vv.y);
            At[(x4+2)*GPT + m] = f2tf32(vv.z);
            At[(x4+3)*GPT + m] = f2tf32(vv.w);
            float4 kk = *(const float4*)(kphi + (size_t)(pos0 + m0 + m) * FF + f0 + x4);
            Bt[(x4+0)*GPT + m] = f2tf32(kk.x);
            Bt[(x4+1)*GPT + m] = f2tf32(kk.y);
            Bt[(x4+2)*GPT + m] = f2tf32(kk.z);
            Bt[(x4+3)*GPT + m] = f2tf32(kk.w);
        }
        __syncthreads();
#pragma unroll
        for (int ks = 0; ks < 4; ks++) {
            int kc = ks * 8 + tig;
            uint32_t af[4][4];
#pragma unroll
            for (int mt = 0; mt < 4; mt++) {
                int base = (wm * 64 + mt * 16 + g) * GPT + kc;
                af[mt][0] = At[base];
                af[mt][1] = At[base + 8 * GPT];
                af[mt][2] = At[base + 4];
                af[mt][3] = At[base + 8 * GPT + 4];
            }
            uint32_t bf[4][2];
#pragma unroll
            for (int nt = 0; nt < 4; nt++) {
                int base = (wn * 32 + nt * 8 + g) * GPT + kc;
                bf[nt][0] = Bt[base];
                bf[nt][1] = Bt[base + 4];
            }
#pragma unroll
            for (int mt = 0; mt < 4; mt++)
#pragma unroll
                for (int nt = 0; nt < 4; nt++)
                    mma8(acc[mt][nt], af[mt], bf[nt]);
        }
        __syncthreads();
    }

    float* S = P + ((size_t)(h * (NC + 1)) + (c + 1)) * FD;
#pragma unroll
    for (int mt = 0; mt < 4; mt++) {
#pragma unroll
        for (int nt = 0; nt < 4; nt++) {
            int d   = wm * 64 + mt * 16 + g;
            int col = f0 + wn * 32 + nt * 8 + tig * 2;
            float2 o01; o01.x = acc[mt][nt][0]; o01.y = acc[mt][nt][1];
            float2 o23; o23.x = acc[mt][nt][2]; o23.y = acc[mt][nt][3];
            *(float2*)(S + (size_t)d * FF + col)       = o01;
            *(float2*)(S + (size_t)(d + 8) * FF + col) = o23;
        }
    }
}

// ---------------------------------------------------------------------------
// Inclusive prefix over chunk slabs.
// ---------------------------------------------------------------------------
__global__ void prefix_kernel(float* __restrict__ P)
{
    const int h = blockIdx.y;
    const int e = blockIdx.x * 256 + threadIdx.x;
    float* base = P + (size_t)h * (NC + 1) * FD;
    base[e] = 0.f;
    float acc = 0.f;
#pragma unroll
    for (int c = 1; c <= NC; c++) {
        acc += base[(size_t)c * FD + e];
        base[(size_t)c * FD + e] = acc;
    }
}

// ---------------------------------------------------------------------------
// output_tc (verified R7): per (head, chunk) block, all-tensor-core.
// ---------------------------------------------------------------------------
#define OSM_BYTES ((128*AP + 128*VP) * 4)   // 135680

__global__ __launch_bounds__(256, 1) void output_tc(
    const float* __restrict__ qphi, const float* __restrict__ kphi,
    const float* __restrict__ vin,  const float* __restrict__ P,
    float* __restrict__ out)
{
    extern __shared__ uint32_t smx[];
    uint32_t* Abuf = smx;
    uint32_t* Vt   = smx + 128 * AP;
    uint32_t* S1Q  = Vt;
    uint32_t* S1K  = Vt + 128 * GP;
    uint32_t* S3Q  = Abuf;
    uint32_t* S3B1 = Abuf + 128 * GP;
    uint32_t* S3B2 = Abuf + 2 * 128 * GP;

    const int t    = threadIdx.x;
    const int lane = t & 31;
    const int wid  = t >> 5;
    const int wm   = wid >> 2;
    const int wn   = wid & 3;
    const int g    = lane >> 2;
    const int tig  = lane & 3;
    const int hc   = blockIdx.x;
    const int h    = hc >> 5;
    const int c    = hc & 31;
    const int pos0 = h * SEQ + c * CHK;

    float accA[4][4][4];
#pragma unroll
    for (int mt = 0; mt < 4; mt++)
#pragma unroll
        for (int nt = 0; nt < 4; nt++)
#pragma unroll
            for (int e = 0; e < 4; e++) accA[mt][nt][e] = 0.f;

    for (int f0 = 0; f0 < FF; f0 += 32) {
        __syncthreads();
#pragma unroll
        for (int r = 0; r < 4; r++) {
            int slot = t + r * 256;
            int row  = slot >> 3;
            int c4   = (slot & 7) << 2;
            float4 qv = *(const float4*)(qphi + (size_t)(pos0 + row) * FF + f0 + c4);
            uint32_t* pq = &S1Q[row * GP + c4];
            pq[0] = f2tf32(qv.x); pq[1] = f2tf32(qv.y);
            pq[2] = f2tf32(qv.z); pq[3] = f2tf32(qv.w);
            float4 kv = *(const float4*)(kphi + (size_t)(pos0 + row) * FF + f0 + c4);
            uint32_t* pk = &S1K[row * GP + c4];
            pk[0] = f2tf32(kv.x); pk[1] = f2tf32(kv.y);
            pk[2] = f2tf32(kv.z); pk[3] = f2tf32(kv.w);
        }
        __syncthreads();
#pragma unroll
        for (int ks = 0; ks < 4; ks++) {
            int kc = ks * 8 + tig;
            uint32_t af[4][4];
#pragma unroll
            for (int mt = 0; mt < 4; mt++) {
                int base = (wm * 64 + mt * 16 + g) * GP + kc;
                af[mt][0] = S1Q[base];
                af[mt][1] = S1Q[base + 8 * GP];
                af[mt][2] = S1Q[base + 4];
                af[mt][3] = S1Q[base + 8 * GP + 4];
            }
            uint32_t bf[4][2];
#pragma unroll
            for (int nt = 0; nt < 4; nt++) {
                int base = (wn * 32 + nt * 8 + g) * GP + kc;
                bf[nt][0] = S1K[base];
                bf[nt][1] = S1K[base + 4];
            }
#pragma unroll
            for (int mt = 0; mt < 4; mt++)
#pragma unroll
                for (int nt = 0; nt < 4; nt++)
                    mma8(accA[mt][nt], af[mt], bf[nt]);
        }
    }
    __syncthreads();

#pragma unroll
    for (int mt = 0; mt < 4; mt++) {
#pragma unroll
        for (int nt = 0; nt < 4; nt++) {
            int n0 = wm * 64 + mt * 16 + g;
            int m0 = wn * 32 + nt * 8 + tig * 2;
            Abuf[n0 * AP + m0]           = f2tf32(accA[mt][nt][0]);
            Abuf[n0 * AP + m0 + 1]       = f2tf32(accA[mt][nt][1]);
            Abuf[(n0 + 8) * AP + m0]     = f2tf32(accA[mt][nt][2]);
            Abuf[(n0 + 8) * AP + m0 + 1] = f2tf32(accA[mt][nt][3]);
        }
    }
#pragma unroll
    for (int r = 0; r < 16; r++) {
        int slot = t + r * 256;
        int m    = slot >> 5;
        int d4   = (slot & 31) << 2;
        float4 vv = *(const float4*)(vin + (size_t)(pos0 + m) * DD + d4);
        Vt[(d4+0)*VP + m] = f2tf32(vv.x);
        Vt[(d4+1)*VP + m] = f2tf32(vv.y);
        Vt[(d4+2)*VP + m] = f2tf32(vv.z);
        Vt[(d4+3)*VP + m] = f2tf32(vv.w);
    }
    __syncthreads();

    float acc1[4][4][4], acc2[4][4][4];
#pragma unroll
    for (int mt = 0; mt < 4; mt++)
#pragma unroll
        for (int nt = 0; nt < 4; nt++)
#pragma unroll
            for (int e = 0; e < 4; e++) { acc1[mt][nt][e] = 0.f; acc2[mt][nt][e] = 0.f; }

#pragma unroll
    for (int kch = 0; kch < 4; kch++) {
#pragma unroll
        for (int ks = 0; ks < 4; ks++) {
            int kc = kch * 32 + ks * 8 + tig;
            uint32_t lo[4][4], up[4][4];
#pragma unroll
            for (int mt = 0; mt < 4; mt++) {
                int nA = wm * 64 + mt * 16 + g;
                int nB = nA + 8;
                uint32_t a0 = Abuf[nA * AP + kc];
                uint32_t a1 = Abuf[nB * AP + kc];
                uint32_t a2 = Abuf[nA * AP + kc + 4];
                uint32_t a3 = Abuf[nB * AP + kc + 4];
                lo[mt][0] = (kc     <= nA) ? a0 : 0u;
                lo[mt][1] = (kc     <= nB) ? a1 : 0u;
                lo[mt][2] = (kc + 4 <= nA) ? a2 : 0u;
                lo[mt][3] = (kc + 4 <= nB) ? a3 : 0u;
                up[mt][0] = (kc     >= nA) ? a0 : 0u;
                up[mt][1] = (kc     >= nB) ? a1 : 0u;
                up[mt][2] = (kc + 4 >= nA) ? a2 : 0u;
                up[mt][3] = (kc + 4 >= nB) ? a3 : 0u;
            }
            uint32_t bf[4][2];
#pragma unroll
            for (int nt = 0; nt < 4; nt++) {
                int base = (wn * 32 + nt * 8 + g) * VP + kc;
                bf[nt][0] = Vt[base];
                bf[nt][1] = Vt[base + 4];
            }
#pragma unroll
            for (int mt = 0; mt < 4; mt++)
#pragma unroll
                for (int nt = 0; nt < 4; nt++) {
                    mma8(acc1[mt][nt], lo[mt], bf[nt]);
                    mma8(acc2[mt][nt], up[mt], bf[nt]);
                }
        }
    }
    __syncthreads();

    const float* Pbase = P + (size_t)h * (NC + 1) * FD;
    const float* Pexc  = Pbase + (size_t)c * FD;
    const float* Pinc  = Pbase + (size_t)(c + 1) * FD;
    const float* Ptot  = Pbase + (size_t)NC * FD;

    for (int f0 = 0; f0 < FF; f0 += 32) {
#pragma unroll
        for (int r = 0; r < 4; r++) {
            int slot = t + r * 256;
            int row  = slot >> 3;
            int c4   = (slot & 7) << 2;
            float4 qv = *(const float4*)(qphi + (size_t)(pos0 + row) * FF + f0 + c4);
            uint32_t* pq = &S3Q[row * GP + c4];
            pq[0] = f2tf32(qv.x); pq[1] = f2tf32(qv.y);
            pq[2] = f2tf32(qv.z); pq[3] = f2tf32(qv.w);
            size_t go = (size_t)row * FF + f0 + c4;
            float4 ev = *(const float4*)(Pexc + go);
            uint32_t* p1 = &S3B1[row * GP + c4];
            p1[0] = f2tf32(ev.x); p1[1] = f2tf32(ev.y);
            p1[2] = f2tf32(ev.z); p1[3] = f2tf32(ev.w);
            float4 iv = *(const float4*)(Pinc + go);
            float4 tv = *(const float4*)(Ptot + go);
            uint32_t* p2 = &S3B2[row * GP + c4];
            p2[0] = f2tf32(tv.x - iv.x); p2[1] = f2tf32(tv.y - iv.y);
            p2[2] = f2tf32(tv.z - iv.z); p2[3] = f2tf32(tv.w - iv.w);
        }
        __syncthreads();
#pragma unroll
        for (int ks = 0; ks < 4; ks++) {
            int kc = ks * 8 + tig;
            uint32_t af[4][4];
#pragma unroll
            for (int mt = 0; mt < 4; mt++) {
                int base = (wm * 64 + mt * 16 + g) * GP + kc;
                af[mt][0] = S3Q[base];
                af[mt][1] = S3Q[base + 8 * GP];
                af[mt][2] = S3Q[base + 4];
                af[mt][3] = S3Q[base + 8 * GP + 4];
            }
            uint32_t b1[4][2], b2[4][2];
#pragma unroll
            for (int nt = 0; nt < 4; nt++) {
                int base = (wn * 32 + nt * 8 + g) * GP + kc;
                b1[nt][0] = S3B1[base];
                b1[nt][1] = S3B1[base + 4];
                b2[nt][0] = S3B2[base];
                b2[nt][1] = S3B2[base + 4];
            }
#pragma unroll
            for (int mt = 0; mt < 4; mt++)
#pragma unroll
                for (int nt = 0; nt < 4; nt++) {
                    mma8(acc1[mt][nt], af[mt], b1[nt]);
                    mma8(acc2[mt][nt], af[mt], b2[nt]);
                }
        }
        __syncthreads();
    }

#pragma unroll
    for (int mt = 0; mt < 4; mt++) {
#pragma unroll
        for (int nt = 0; nt < 4; nt++) {
            int n0  = wm * 64 + mt * 16 + g;
            int d0  = wn * 32 + nt * 8 + tig * 2;
            int posA = c * CHK + n0;
            int posB = posA + 8;
            float s1a = 1.f / (float)(posA + 1);
            float s2a = 1.f / (float)(SEQ - posA);
            float s1b = 1.f / (float)(posB + 1);
            float s2b = 1.f / (float)(SEQ - posB);
            float2 oA, oB;
            oA.x = acc1[mt][nt][0] * s1a + acc2[mt][nt][0] * s2a;
            oA.y = acc1[mt][nt][1] * s1a + acc2[mt][nt][1] * s2a;
            oB.x = acc1[mt][nt][2] * s1b + acc2[mt][nt][2] * s2b;
            oB.y = acc1[mt][nt][3] * s1b + acc2[mt][nt][3] * s2b;
            *(float2*)(out + (size_t)(pos0 + n0) * DD + d0)     = oA;
            *(float2*)(out + (size_t)(pos0 + n0 + 8) * DD + d0) = oB;
        }
    }
}

// ---------------------------------------------------------------------------
extern "C" void kernel_launch(void* const* d_in, const int* in_sizes, int n_in,
                              void* d_out, int out_size)
{
    (void)out_size;
    int big[3] = {0, 1, 2}; int nbig = 0;
    int iw1 = -1, iw2 = -1, ibias[2] = {-1, -1}; int nb = 0;
    for (int i = 0; i < n_in; i++) {
        long long s = in_sizes[i];
        if ((s == 12582912LL || s == 50331648LL) && nbig < 3) big[nbig++] = i;
        else if (s == 32768LL  || s == 131072LL) iw1 = i;
        else if (s == 65536LL  || s == 262144LL) iw2 = i;
        else if ((s == 256LL   || s == 1024LL) && nb < 2) ibias[nb++] = i;
    }
    if (nbig != 3 || iw1 < 0 || iw2 < 0 || nb != 2) {
        big[0] = 0; big[1] = 1; big[2] = 2;
        iw1 = 3; ibias[0] = 4; iw2 = 5; ibias[1] = 6;
    }
    const float *q, *k;
    if (big[0] == 0) {
        q = (const float*)d_in[big[0]];
        k = (const float*)d_in[big[1]];
    } else {
        k = (const float*)d_in[big[0]];
        q = (const float*)d_in[big[1]];
    }
    const float* v  = (const float*)d_in[big[2]];
    const float* w1 = (const float*)d_in[iw1];
    const float* b1 = (const float*)d_in[ibias[0]];
    const float* w2 = (const float*)d_in[iw2];
    const float* b2 = (const float*)d_in[ibias[1]];
    float* out = (float*)d_out;

    float *hq, *hk, *qphi, *kphi, *P, *w1t, *w2t;
    cudaGetSymbolAddress((void**)&hq,   g_hq);
    cudaGetSymbolAddress((void**)&hk,   g_hk);
    cudaGetSymbolAddress((void**)&qphi, g_qphi);
    cudaGetSymbolAddress((void**)&kphi, g_kphi);
    cudaGetSymbolAddress((void**)&P,    g_P);
    cudaGetSymbolAddress((void**)&w1t,  g_w1t);
    cudaGetSymbolAddress((void**)&w2t,  g_w2t);

    cudaFuncSetAttribute(phiA,
                         cudaFuncAttributeMaxDynamicSharedMemorySize, PA_BYTES);
    cudaFuncSetAttribute(phiB,
                         cudaFuncAttributeMaxDynamicSharedMemorySize, PB_BYTES);
    cudaFuncSetAttribute(output_tc,
                         cudaFuncAttributeMaxDynamicSharedMemorySize, OSM_BYTES);

    transpose_kernel<<<(DD*FF + 255)/256, 256>>>(w1, w1t, DD, FF);
    transpose_kernel<<<(FF*FF + 255)/256, 256>>>(w2, w2t, FF, FF);

    phiA<<<2 * NBLK, 256, PA_BYTES>>>(q, k, w1t, b1, hq, hk);
    phiB<<<2 * NBLK, 256, PB_BYTES>>>(hq, hk, w2t, b2, qphi, kphi);

    chunk_state_tc<<<dim3(BH * NC, 2), 256>>>(kphi, v, P);
    prefix_kernel<<<dim3(FD / 256, BH), 256>>>(P);

    output_tc<<<BH * NC, 256, OSM_BYTES>>>(qphi, kphi, v, P, out);
}